// round 14
// baseline (speedup 1.0000x reference)
#include <cuda_runtime.h>
#include <cuda_fp16.h>
#include <cstdint>

#define HW 4096
#define DDIM 64
#define NSLICE 256          // total K slices of 16
#define HSLICE 128          // slices per K-half
#define NBLK 64             // 32-wide K blocks per K-half
#define NCTA 296            // 2 CTAs per SM exactly
#define TOTROWS 16384       // 4 batches x 4096 rows
#define CS_STRIDE 66

// B fragments, lane-major: g_fp[slice][q][lane][4 x b32]; uint4 index = s*128 + q*32 + l
// ISA->real K map (per 32-block, full-line A loads): real = 8*(l&3) + 4*(s&1) + 2*pair + t
__device__ uint32_t g_fp[NSLICE * 4 * 32 * 4];

// ---------------------------------------------------------------------------
// Kernel 1: build packed B fragments of f[m,d] = cos(8pi*(w0*gx + w1*gy + b))
// ---------------------------------------------------------------------------
__global__ void pos_enc_kernel(const float* __restrict__ w,
                               const float* __restrict__ bias) {
    int idx = blockIdx.x * blockDim.x + threadIdx.x;
    if (idx >= NSLICE * 512) return;
    int c    = idx & 3;
    int l    = (idx >> 2) & 31;
    int q    = (idx >> 7) & 3;
    int gs   = idx >> 9;
    int j    = q * 2 + (c >> 1);
    int pair = c & 1;
    int d    = j * 8 + (l >> 2);
    int m0   = (gs >> 1) * 32 + ((l & 3) << 3) + ((gs & 1) << 2) + (pair << 1);
    float w0 = w[2 * d], w1 = w[2 * d + 1], bd = bias[d];
    float v[2];
#pragma unroll
    for (int t = 0; t < 2; t++) {
        int m = m0 + t;
        int x = m & 63, y = m >> 6;
        float gx = (float)(2 * x - 63) * (1.0f / 64.0f);
        float gy = (float)(2 * y - 63) * (1.0f / 64.0f);
        v[t] = cosf(25.132741228718345f * fmaf(w0, gx, fmaf(w1, gy, bd)));
    }
    __half2 h = __floats2half2_rn(v[0], v[1]);
    g_fp[idx] = *reinterpret_cast<uint32_t*>(&h);
}

// ---------------------------------------------------------------------------
// exp(x),exp(y) packed fp16 via ex2.approx.f16x2 (lo=exp(x), hi=exp(y))
#define E2PH(dst, x, y)                                                         \
    do {                                                                        \
        float _fa = (x) * 1.4426950408889634f;                                  \
        float _fb = (y) * 1.4426950408889634f;                                  \
        asm("cvt.rn.f16x2.f32 %0, %1, %2;" : "=r"(dst) : "f"(_fb), "f"(_fa));   \
        asm("ex2.approx.f16x2 %0, %0;" : "+r"(dst));                            \
    } while (0)

#define MMA(dst, a0, a1, a2, a3, b0, b1)                                        \
    asm volatile("mma.sync.aligned.m16n8k16.row.col.f32.f16.f16.f32 "           \
                 "{%0,%1,%2,%3},{%4,%5,%6,%7},{%8,%9},{%0,%1,%2,%3};"           \
                 : "+f"(dst[0]), "+f"(dst[1]), "+f"(dst[2]), "+f"(dst[3])       \
                 : "r"(a0), "r"(a1), "r"(a2), "r"(a3), "r"(b0), "r"(b1))

// Load one 32-wide K block (row-clamped pointers pA0/pA1)
#define LA(st, b)                                                               \
    do { const float* _p0 = pA0 + (size_t)(b) * 32;                             \
         const float* _p1 = pA1 + (size_t)(b) * 32;                             \
        R[st][0] = __ldcs((const float4*)_p0);                                  \
        R[st][1] = __ldcs((const float4*)(_p0 + 4));                            \
        R[st][2] = __ldcs((const float4*)_p1);                                  \
        R[st][3] = __ldcs((const float4*)(_p1 + 4)); } while (0)

// One 16-slice: on-demand B, f16x2 exp, 9 MMAs
#define HALF_STAGE(sidx, rl, rh, do_la, st, blk)                                \
    do {                                                                        \
        const uint4* _bp = pB + (size_t)(sidx) * 128;                           \
        uint4 B0 = __ldg(_bp);      uint4 B1 = __ldg(_bp + 32);                 \
        uint4 B2 = __ldg(_bp + 64); uint4 B3 = __ldg(_bp + 96);                 \
        uint32_t ra0, ra1, ra2, ra3;                                            \
        E2PH(ra0, rl.x, rl.y);                                                  \
        E2PH(ra2, rl.z, rl.w);                                                  \
        E2PH(ra1, rh.x, rh.y);                                                  \
        E2PH(ra3, rh.z, rh.w);                                                  \
        if (do_la && (blk) + 2 < NBLK) LA(st, (blk) + 2);                       \
        MMA(acc[0], ra0, ra1, ra2, ra3, B0.x, B0.y);                            \
        MMA(acc[1], ra0, ra1, ra2, ra3, B0.z, B0.w);                            \
        MMA(acc[2], ra0, ra1, ra2, ra3, B1.x, B1.y);                            \
        MMA(acc[3], ra0, ra1, ra2, ra3, B1.z, B1.w);                            \
        MMA(acc[4], ra0, ra1, ra2, ra3, B2.x, B2.y);                            \
        MMA(acc[5], ra0, ra1, ra2, ra3, B2.z, B2.w);                            \
        MMA(acc[6], ra0, ra1, ra2, ra3, B3.x, B3.y);                            \
        MMA(acc[7], ra0, ra1, ra2, ra3, B3.z, B3.w);                            \
        MMA(acc[8], ra0, ra1, ra2, ra3, bz, bz);                                \
    } while (0)

#define STAGE(st, blk)                                                          \
    do {                                                                        \
        HALF_STAGE(2 * (blk),     R[st][0], R[st][2], 0, st, blk);              \
        HALF_STAGE(2 * (blk) + 1, R[st][1], R[st][3], 1, st, blk);              \
    } while (0)

// ---------------------------------------------------------------------------
// Kernel 2: 296 CTAs (exactly 2/SM), CTA owns global rows [rs, re) (55-56 rows)
// inside a 64-row frame; overflow lanes clamp to re-1 (L1-absorbed).
// 8 warps = 4 row-groups x 2 K-halves; R13 mainloop (f16x2 exp, Z via 9th MMA).
// ---------------------------------------------------------------------------
__global__ __launch_bounds__(256, 2)
void gp_kernel(const float* __restrict__ sim, float* __restrict__ out) {
    __shared__ float Cs[64][CS_STRIDE];
    __shared__ float Zs[64];
    __shared__ float Zr[64];

    const int tid = threadIdx.x;
    const int l   = tid & 31;
    const int w   = tid >> 5;
    const int wm  = w & 3;       // row group
    const int kh  = w >> 2;      // K half
    const int cta = blockIdx.x;
    const int rs  = (TOTROWS * cta) / NCTA;
    const int re  = (TOTROWS * (cta + 1)) / NCTA;

    const int g0  = rs + wm * 16 + (l >> 2);
    const int g0c = min(g0, re - 1);
    const int g1c = min(g0 + 8, re - 1);

    const float* pA0 = sim + (size_t)g0c * HW + kh * (HSLICE * 16) + (l & 3) * 8;
    const float* pA1 = sim + (size_t)g1c * HW + kh * (HSLICE * 16) + (l & 3) * 8;
    const uint4* pB  = ((const uint4*)g_fp) + (size_t)kh * HSLICE * 128 + l;

    float acc[9][4];
#pragma unroll
    for (int i = 0; i < 9; i++)
#pragma unroll
        for (int k = 0; k < 4; k++) acc[i][k] = 0.0f;

    const uint32_t bz = (l < 4) ? 0x3C003C00u : 0u;  // ones in B col n=0

    float4 R[2][4];
    LA(0, 0); LA(1, 1);

#pragma unroll 1
    for (int b = 0; b < NBLK; b += 2) {
        STAGE(0, b);
        STAGE(1, b + 1);
    }

    // ---- epilogue: merge K-halves via smem, divide by Z, per-row store ----
    const int lr = wm * 16 + (l >> 2);
    if (kh == 0) {
#pragma unroll
        for (int j = 0; j < 8; j++) {
            const int c0 = j * 8 + (l & 3) * 2;
            *(float2*)&Cs[lr][c0]     = make_float2(acc[j][0], acc[j][1]);
            *(float2*)&Cs[lr + 8][c0] = make_float2(acc[j][2], acc[j][3]);
        }
        if ((l & 3) == 0) { Zs[lr] = acc[8][0]; Zs[lr + 8] = acc[8][2]; }
    }
    __syncthreads();
    if (kh == 1) {
#pragma unroll
        for (int j = 0; j < 8; j++) {
            const int c0 = j * 8 + (l & 3) * 2;
            Cs[lr][c0]         += acc[j][0];
            Cs[lr][c0 + 1]     += acc[j][1];
            Cs[lr + 8][c0]     += acc[j][2];
            Cs[lr + 8][c0 + 1] += acc[j][3];
        }
        if ((l & 3) == 0) { Zs[lr] += acc[8][0]; Zs[lr + 8] += acc[8][2]; }
    }
    __syncthreads();
    if (tid < 64) Zr[tid] = 1.0f / Zs[tid];
    __syncthreads();

    {
        const int d = tid >> 2, seg = tid & 3;
        const int ci = re - rs;
#pragma unroll
        for (int i = 0; i < 16; i++) {
            const int n = seg * 16 + i;
            if (n < ci) {
                const int g = rs + n;
                out[((size_t)((g >> 12) * DDIM + d)) * HW + (g & (HW - 1))] =
                    Cs[n][d] * Zr[n];
            }
        }
    }
}

// ---------------------------------------------------------------------------
extern "C" void kernel_launch(void* const* d_in, const int* in_sizes, int n_in,
                              void* d_out, int out_size) {
    const float* sim  = (const float*)d_in[0];  // [4, 4096, 4096] fp32
    const float* w    = (const float*)d_in[1];  // [64, 2] fp32
    const float* bias = (const float*)d_in[2];  // [64] fp32
    float* out = (float*)d_out;                 // [4, 64, 64, 64] fp32

    pos_enc_kernel<<<(NSLICE * 512 + 255) / 256, 256>>>(w, bias);

    gp_kernel<<<NCTA, 256>>>(sim, out);
}